// round 2
// baseline (speedup 1.0000x reference)
#include <cuda_runtime.h>
#include <cuda_fp16.h>
#include <cstdint>
#include <cstddef>

// ---------------------------------------------------------------------------
// GPT-2 transformer block, fp16 tensor-core (mma.sync) implementation.
// B=4, S=2048, D=1024, H=16, hd=64, DFF=4096. fp32 in/out, fp16 compute,
// fp32 accumulation everywhere.
// ---------------------------------------------------------------------------

#define BATCH  4
#define SEQ    2048
#define DMODEL 1024
#define NHEAD  16
#define HDIM   64
#define DFF    4096
#define ROWS   (BATCH * SEQ)   // 8192

// -------------------------- scratch (device globals) ----------------------
__device__ __half g_x16    [(size_t)ROWS * DMODEL];
__device__ __half g_wattnT [(size_t)3 * DMODEL * DMODEL];   // [3D][D]
__device__ __half g_waprojT[(size_t)DMODEL * DMODEL];       // [D][D]
__device__ __half g_wfcT   [(size_t)DFF * DMODEL];          // [DFF][D]
__device__ __half g_wmprojT[(size_t)DMODEL * DFF];          // [D][DFF]
__device__ __half g_q16    [(size_t)ROWS * DMODEL];         // [B*H][S][hd]
__device__ __half g_k16    [(size_t)ROWS * DMODEL];
__device__ __half g_v16    [(size_t)ROWS * DMODEL];
__device__ __half g_a16    [(size_t)ROWS * DMODEL];         // attn out, [r][D]
__device__ float  g_ap32   [(size_t)ROWS * DMODEL];
__device__ float  g_n32    [(size_t)ROWS * DMODEL];
__device__ __half g_n16    [(size_t)ROWS * DMODEL];
__device__ __half g_h16    [(size_t)ROWS * DFF];
__device__ float  g_m32    [(size_t)ROWS * DMODEL];

// ------------------------------ helpers -----------------------------------
__device__ __forceinline__ void mma16816(float c[4], const uint32_t a[4],
                                         const uint32_t b[2]) {
    asm volatile(
        "mma.sync.aligned.m16n8k16.row.col.f32.f16.f16.f32 "
        "{%0,%1,%2,%3}, {%4,%5,%6,%7}, {%8,%9}, {%0,%1,%2,%3};\n"
        : "+f"(c[0]), "+f"(c[1]), "+f"(c[2]), "+f"(c[3])
        : "r"(a[0]), "r"(a[1]), "r"(a[2]), "r"(a[3]), "r"(b[0]), "r"(b[1]));
}

__device__ __forceinline__ void cp_async16(void* smem, const void* gptr) {
    uint32_t s = (uint32_t)__cvta_generic_to_shared(smem);
    asm volatile("cp.async.cg.shared.global [%0], [%1], 16;\n" ::"r"(s), "l"(gptr));
}
#define CP_COMMIT() asm volatile("cp.async.commit_group;\n" ::)
#define CP_WAIT1()  asm volatile("cp.async.wait_group 1;\n" ::)

__device__ __forceinline__ uint32_t pack_half2f(float a, float b) {
    __half2 h = __floats2half2_rn(a, b);
    return *reinterpret_cast<uint32_t*>(&h);
}

__device__ __forceinline__ float gelu_f(float x) {
    const float k0 = 0.7978845608028654f;  // sqrt(2/pi)
    float t = tanhf(k0 * (x + 0.044715f * x * x * x));
    return 0.5f * x * (1.0f + t);
}

// ------------------------- conversion kernels -----------------------------
__global__ void cvt_f32_to_f16(const float* __restrict__ in,
                               __half* __restrict__ out, int n) {
    int i = blockIdx.x * blockDim.x + threadIdx.x;
    if (i < n) out[i] = __float2half(in[i]);
}

// in: [R][C] fp32 row-major  ->  out: [C][R] fp16
__global__ void transpose_cvt(const float* __restrict__ in,
                              __half* __restrict__ out, int R, int C) {
    __shared__ float t[32][33];
    int c = blockIdx.x * 32 + threadIdx.x;
    int r = blockIdx.y * 32 + threadIdx.y;
#pragma unroll
    for (int i = 0; i < 32; i += 8)
        t[threadIdx.y + i][threadIdx.x] = in[(size_t)(r + i) * C + c];
    __syncthreads();
    int oc   = blockIdx.y * 32 + threadIdx.x;   // output col = original row
    int orow = blockIdx.x * 32 + threadIdx.y;   // output row = original col
#pragma unroll
    for (int i = 0; i < 32; i += 8)
        out[(size_t)(orow + i) * R + oc] = __float2half(t[threadIdx.x][threadIdx.y + i]);
}

// ------------------------------- GEMM -------------------------------------
// C[M,N] = A[M,K] (fp16 row-major) * Bt[N,K] (fp16, i.e. B col-major) + bias
// BM=BN=128, BK=32, 256 threads, warp grid 2x4, warp tile 64x32.
#define GB_BM 128
#define GB_BN 128
#define GB_BK 32
#define GB_LK 40   // padded shared K stride (halves)

enum { EPI_QKV = 0, EPI_F32 = 1, EPI_GELU = 2 };

template <int EPI>
__global__ __launch_bounds__(256, 2) void gemm_kernel(
    const __half* __restrict__ A, const __half* __restrict__ Bt,
    const float* __restrict__ bias,
    float* __restrict__ outF, __half* __restrict__ outH,
    __half* __restrict__ oq, __half* __restrict__ ok, __half* __restrict__ ov,
    int M, int N, int K) {
    __shared__ __half As[2][GB_BM][GB_LK];
    __shared__ __half Bs[2][GB_BN][GB_LK];

    const int tid  = threadIdx.x;
    const int warp = tid >> 5, lane = tid & 31;
    const int g = lane >> 2, tg = lane & 3;
    const int wm = warp >> 2, wn = warp & 3;
    const int bm = blockIdx.y * GB_BM, bn = blockIdx.x * GB_BN;

    float acc[4][4][4];
#pragma unroll
    for (int i = 0; i < 4; i++)
#pragma unroll
        for (int j = 0; j < 4; j++)
#pragma unroll
            for (int q = 0; q < 4; q++) acc[i][j][q] = 0.f;

    const int KT = K / GB_BK;

    auto load_tile = [&](int kt, int buf) {
        int k0 = kt * GB_BK;
#pragma unroll
        for (int i = 0; i < 2; i++) {
            int c   = tid + i * 256;
            int row = c >> 2;
            int kc  = (c & 3) * 8;
            cp_async16(&As[buf][row][kc], &A[(size_t)(bm + row) * K + k0 + kc]);
            cp_async16(&Bs[buf][row][kc], &Bt[(size_t)(bn + row) * K + k0 + kc]);
        }
    };

    load_tile(0, 0); CP_COMMIT();
    load_tile(1, 1); CP_COMMIT();

    for (int t = 0; t < KT; t++) {
        CP_WAIT1();
        __syncthreads();
        int buf = t & 1;
#pragma unroll
        for (int kk = 0; kk < 2; kk++) {
            int kb = kk * 16 + tg * 2;
            uint32_t a[4][4], b[4][2];
#pragma unroll
            for (int mi = 0; mi < 4; mi++) {
                int r = wm * 64 + mi * 16 + g;
                a[mi][0] = *reinterpret_cast<const uint32_t*>(&As[buf][r][kb]);
                a[mi][1] = *reinterpret_cast<const uint32_t*>(&As[buf][r + 8][kb]);
                a[mi][2] = *reinterpret_cast<const uint32_t*>(&As[buf][r][kb + 8]);
                a[mi][3] = *reinterpret_cast<const uint32_t*>(&As[buf][r + 8][kb + 8]);
            }
#pragma unroll
            for (int ni = 0; ni < 4; ni++) {
                int c = wn * 32 + ni * 8 + g;
                b[ni][0] = *reinterpret_cast<const uint32_t*>(&Bs[buf][c][kb]);
                b[ni][1] = *reinterpret_cast<const uint32_t*>(&Bs[buf][c][kb + 8]);
            }
#pragma unroll
            for (int mi = 0; mi < 4; mi++)
#pragma unroll
                for (int ni = 0; ni < 4; ni++) mma16816(acc[mi][ni], a[mi], b[ni]);
        }
        __syncthreads();
        if (t + 2 < KT) load_tile(t + 2, buf);
        CP_COMMIT();
    }

    // ------------------------------ epilogue -------------------------------
#pragma unroll
    for (int mi = 0; mi < 4; mi++) {
        int r0 = bm + wm * 64 + mi * 16 + g;
        int r1 = r0 + 8;
#pragma unroll
        for (int ni = 0; ni < 4; ni++) {
            int c0 = bn + wn * 32 + ni * 8 + tg * 2;
            float bv0 = bias[c0], bv1 = bias[c0 + 1];
            float v00 = acc[mi][ni][0] + bv0, v01 = acc[mi][ni][1] + bv1;
            float v10 = acc[mi][ni][2] + bv0, v11 = acc[mi][ni][3] + bv1;
            if (EPI == EPI_F32) {
                outF[(size_t)r0 * N + c0]     = v00;
                outF[(size_t)r0 * N + c0 + 1] = v01;
                outF[(size_t)r1 * N + c0]     = v10;
                outF[(size_t)r1 * N + c0 + 1] = v11;
            } else if (EPI == EPI_GELU) {
                outH[(size_t)r0 * N + c0]     = __float2half(gelu_f(v00));
                outH[(size_t)r0 * N + c0 + 1] = __float2half(gelu_f(v01));
                outH[(size_t)r1 * N + c0]     = __float2half(gelu_f(v10));
                outH[(size_t)r1 * N + c0 + 1] = __float2half(gelu_f(v11));
            } else {  // EPI_QKV: scatter into per-head [B*H][S][hd] layout
#pragma unroll
                for (int e = 0; e < 4; e++) {
                    int r = (e < 2) ? r0 : r1;
                    int c = c0 + (e & 1);
                    float val = (e == 0) ? v00 : (e == 1) ? v01 : (e == 2) ? v10 : v11;
                    int which = c >> 10;
                    int cc = c & 1023;
                    int h = cc >> 6, d = cc & 63;
                    int b = r >> 11, s = r & 2047;
                    size_t idx = ((size_t)(b * NHEAD + h) * SEQ + s) * HDIM + d;
                    __half* dst = which == 0 ? oq : which == 1 ? ok : ov;
                    dst[idx] = __float2half(val);
                }
            }
        }
    }
}

// --------------------------- flash attention -------------------------------
// grid (S/128, B*H), 256 threads (8 warps x 16 query rows). Causal.
#define AT_BQ 128
#define AT_BK 128
#define AT_LK 72    // Ks row stride (halves)
#define AT_LV 138   // Vt row stride (halves)

__global__ __launch_bounds__(256, 1) void attn_kernel(
    const __half* __restrict__ Q, const __half* __restrict__ K,
    const __half* __restrict__ V, __half* __restrict__ Aout) {
    __shared__ __half Ks[AT_BK][AT_LK];
    __shared__ __half Vt[HDIM][AT_LV];

    const int tid  = threadIdx.x;
    const int warp = tid >> 5, lane = tid & 31;
    const int g = lane >> 2, tg = lane & 3;
    const int bh = blockIdx.y;
    const int qb = blockIdx.x;
    const size_t base = (size_t)bh * SEQ * HDIM;

    // stage Q tile through Ks, then lift fragments into registers
    for (int i = tid; i < AT_BQ * 8; i += 256) {
        int row = i >> 3, ch = (i & 7) * 8;
        *reinterpret_cast<uint4*>(&Ks[row][ch]) =
            *reinterpret_cast<const uint4*>(&Q[base + (size_t)(qb * AT_BQ + row) * HDIM + ch]);
    }
    __syncthreads();
    uint32_t qa[4][4];
    {
        int r = warp * 16 + g;
#pragma unroll
        for (int kt = 0; kt < 4; kt++) {
            int kb = kt * 16 + tg * 2;
            qa[kt][0] = *reinterpret_cast<const uint32_t*>(&Ks[r][kb]);
            qa[kt][1] = *reinterpret_cast<const uint32_t*>(&Ks[r + 8][kb]);
            qa[kt][2] = *reinterpret_cast<const uint32_t*>(&Ks[r][kb + 8]);
            qa[kt][3] = *reinterpret_cast<const uint32_t*>(&Ks[r + 8][kb + 8]);
        }
    }
    __syncthreads();

    float o[8][4];
#pragma unroll
    for (int i = 0; i < 8; i++)
#pragma unroll
        for (int j = 0; j < 4; j++) o[i][j] = 0.f;
    float m0 = -1e30f, m1 = -1e30f, l0 = 0.f, l1 = 0.f;
    const int q0 = qb * AT_BQ + warp * 16 + g;
    const int q1 = q0 + 8;

    for (int kblk = 0; kblk <= qb; kblk++) {
        // load K tile (k-major) and V tile transposed
        for (int i = tid; i < AT_BK * 8; i += 256) {
            int row = i >> 3, ch = (i & 7) * 8;
            *reinterpret_cast<uint4*>(&Ks[row][ch]) =
                *reinterpret_cast<const uint4*>(&K[base + (size_t)(kblk * AT_BK + row) * HDIM + ch]);
        }
        for (int i = tid; i < AT_BK * HDIM; i += 256) {
            int s = i >> 6, d = i & 63;
            Vt[d][s] = V[base + (size_t)(kblk * AT_BK + s) * HDIM + d];
        }
        __syncthreads();

        // S = Q K^T
        float sacc[16][4];
#pragma unroll
        for (int nt = 0; nt < 16; nt++)
#pragma unroll
            for (int j = 0; j < 4; j++) sacc[nt][j] = 0.f;
#pragma unroll
        for (int kt = 0; kt < 4; kt++) {
#pragma unroll
            for (int nt = 0; nt < 16; nt++) {
                uint32_t b[2];
                int col = nt * 8 + g;
                int kb = kt * 16 + tg * 2;
                b[0] = *reinterpret_cast<const uint32_t*>(&Ks[col][kb]);
                b[1] = *reinterpret_cast<const uint32_t*>(&Ks[col][kb + 8]);
                mma16816(sacc[nt], qa[kt], b);
            }
        }

        // scale + causal mask
        const float scale = 0.125f;  // 1/sqrt(64)
        const int kbase = kblk * AT_BK;
#pragma unroll
        for (int nt = 0; nt < 16; nt++) {
            int c0 = kbase + nt * 8 + tg * 2;
            sacc[nt][0] *= scale; sacc[nt][1] *= scale;
            sacc[nt][2] *= scale; sacc[nt][3] *= scale;
            if (kblk == qb) {
                if (c0 > q0)     sacc[nt][0] = -1e30f;
                if (c0 + 1 > q0) sacc[nt][1] = -1e30f;
                if (c0 > q1)     sacc[nt][2] = -1e30f;
                if (c0 + 1 > q1) sacc[nt][3] = -1e30f;
            }
        }

        // online softmax
        float nm0 = m0, nm1 = m1;
#pragma unroll
        for (int nt = 0; nt < 16; nt++) {
            nm0 = fmaxf(nm0, fmaxf(sacc[nt][0], sacc[nt][1]));
            nm1 = fmaxf(nm1, fmaxf(sacc[nt][2], sacc[nt][3]));
        }
        nm0 = fmaxf(nm0, __shfl_xor_sync(0xffffffffu, nm0, 1));
        nm0 = fmaxf(nm0, __shfl_xor_sync(0xffffffffu, nm0, 2));
        nm1 = fmaxf(nm1, __shfl_xor_sync(0xffffffffu, nm1, 1));
        nm1 = fmaxf(nm1, __shfl_xor_sync(0xffffffffu, nm1, 2));
        float alpha0 = __expf(m0 - nm0), alpha1 = __expf(m1 - nm1);

        float ls0 = 0.f, ls1 = 0.f;
        uint32_t pa[8][4];
#pragma unroll
        for (int nt = 0; nt < 16; nt++) {
            float p00 = __expf(sacc[nt][0] - nm0);
            float p01 = __expf(sacc[nt][1] - nm0);
            float p10 = __expf(sacc[nt][2] - nm1);
            float p11 = __expf(sacc[nt][3] - nm1);
            ls0 += p00 + p01;
            ls1 += p10 + p11;
            int kt = nt >> 1, hi = nt & 1;
            pa[kt][hi * 2 + 0] = pack_half2f(p00, p01);
            pa[kt][hi * 2 + 1] = pack_half2f(p10, p11);
        }
        ls0 += __shfl_xor_sync(0xffffffffu, ls0, 1);
        ls0 += __shfl_xor_sync(0xffffffffu, ls0, 2);
        ls1 += __shfl_xor_sync(0xffffffffu, ls1, 1);
        ls1 += __shfl_xor_sync(0xffffffffu, ls1, 2);
        l0 = l0 * alpha0 + ls0;
        l1 = l1 * alpha1 + ls1;
        m0 = nm0;
        m1 = nm1;
#pragma unroll
        for (int dnt = 0; dnt < 8; dnt++) {
            o[dnt][0] *= alpha0; o[dnt][1] *= alpha0;
            o[dnt][2] *= alpha1; o[dnt][3] *= alpha1;
        }

        // O += P V
#pragma unroll
        for (int kt = 0; kt < 8; kt++) {
#pragma unroll
            for (int dnt = 0; dnt < 8; dnt++) {
                uint32_t b[2];
                int d = dnt * 8 + g;
                b[0] = *reinterpret_cast<const uint32_t*>(&Vt[d][kt * 16 + tg * 2]);
                b[1] = *reinterpret_cast<const uint32_t*>(&Vt[d][kt * 16 + 8 + tg * 2]);
                mma16816(o[dnt], pa[kt], b);
            }
        }
        __syncthreads();
    }

    // write merged-head output a[b,s,h*64+d] as fp16
    float inv0 = 1.f / l0, inv1 = 1.f / l1;
    int b = bh >> 4, h = bh & 15;
    int s0 = qb * AT_BQ + warp * 16 + g;
    size_t r0 = (size_t)(b * SEQ + s0) * DMODEL + h * HDIM;
    size_t r1 = r0 + (size_t)8 * DMODEL;
#pragma unroll
    for (int dnt = 0; dnt < 8; dnt++) {
        int d = dnt * 8 + tg * 2;
        Aout[r0 + d]     = __float2half(o[dnt][0] * inv0);
        Aout[r0 + d + 1] = __float2half(o[dnt][1] * inv0);
        Aout[r1 + d]     = __float2half(o[dnt][2] * inv1);
        Aout[r1 + d + 1] = __float2half(o[dnt][3] * inv1);
    }
}

// --------------------------- residual + layernorm --------------------------
// out = LN(X + Y) * g + b; optionally also emit fp16 copy. One block per row.
__global__ __launch_bounds__(256) void ln_kernel(
    const float* __restrict__ X, const float* __restrict__ Y,
    const float* __restrict__ gg, const float* __restrict__ bb,
    float* __restrict__ out32, __half* __restrict__ out16) {
    const int row = blockIdx.x, tid = threadIdx.x;
    const float* x = X + (size_t)row * DMODEL;
    const float* y = Y + (size_t)row * DMODEL;
    float v[4];
    float s = 0.f;
#pragma unroll
    for (int i = 0; i < 4; i++) {
        int c = tid + i * 256;
        v[i] = x[c] + y[c];
        s += v[i];
    }
    __shared__ float red[8], red2[8];
#pragma unroll
    for (int o = 16; o; o >>= 1) s += __shfl_xor_sync(0xffffffffu, s, o);
    if ((tid & 31) == 0) red[tid >> 5] = s;
    __syncthreads();
    float tot = 0.f;
#pragma unroll
    for (int i = 0; i < 8; i++) tot += red[i];
    float mean = tot * (1.0f / DMODEL);

    float s2 = 0.f;
#pragma unroll
    for (int i = 0; i < 4; i++) {
        float d = v[i] - mean;
        s2 += d * d;
    }
#pragma unroll
    for (int o = 16; o; o >>= 1) s2 += __shfl_xor_sync(0xffffffffu, s2, o);
    if ((tid & 31) == 0) red2[tid >> 5] = s2;
    __syncthreads();
    float tot2 = 0.f;
#pragma unroll
    for (int i = 0; i < 8; i++) tot2 += red2[i];
    float rstd = rsqrtf(tot2 * (1.0f / DMODEL) + 1e-5f);

#pragma unroll
    for (int i = 0; i < 4; i++) {
        int c = tid + i * 256;
        float nv = (v[i] - mean) * rstd * gg[c] + bb[c];
        out32[(size_t)row * DMODEL + c] = nv;
        if (out16) out16[(size_t)row * DMODEL + c] = __float2half(nv);
    }
}

// ------------------------------- host --------------------------------------
extern "C" void kernel_launch(void* const* d_in, const int* in_sizes, int n_in,
                              void* d_out, int out_size) {
    const float* x       = (const float*)d_in[0];
    const float* w_attn  = (const float*)d_in[1];
    const float* b_attn  = (const float*)d_in[2];
    const float* w_aproj = (const float*)d_in[3];
    const float* b_aproj = (const float*)d_in[4];
    const float* g1      = (const float*)d_in[5];
    const float* b1      = (const float*)d_in[6];
    const float* w_fc    = (const float*)d_in[7];
    const float* b_fc    = (const float*)d_in[8];
    const float* w_mproj = (const float*)d_in[9];
    const float* b_mproj = (const float*)d_in[10];
    const float* g2      = (const float*)d_in[11];
    const float* b2      = (const float*)d_in[12];
    float* out = (float*)d_out;

    __half *x16, *wattnT, *waprojT, *wfcT, *wmprojT, *q16, *k16, *v16, *a16, *n16, *h16;
    float *ap32, *n32, *m32;
    cudaGetSymbolAddress((void**)&x16,     g_x16);
    cudaGetSymbolAddress((void**)&wattnT,  g_wattnT);
    cudaGetSymbolAddress((void**)&waprojT, g_waprojT);
    cudaGetSymbolAddress((void**)&wfcT,    g_wfcT);
    cudaGetSymbolAddress((void**)&wmprojT, g_wmprojT);
    cudaGetSymbolAddress((void**)&q16,     g_q16);
    cudaGetSymbolAddress((void**)&k16,     g_k16);
    cudaGetSymbolAddress((void**)&v16,     g_v16);
    cudaGetSymbolAddress((void**)&a16,     g_a16);
    cudaGetSymbolAddress((void**)&n16,     g_n16);
    cudaGetSymbolAddress((void**)&h16,     g_h16);
    cudaGetSymbolAddress((void**)&ap32,    g_ap32);
    cudaGetSymbolAddress((void**)&n32,     g_n32);
    cudaGetSymbolAddress((void**)&m32,     g_m32);

    dim3 tb(32, 8);
    // input + weight conversion (weights transposed to [N][K] fp16)
    cvt_f32_to_f16<<<(ROWS * DMODEL) / 256, 256>>>(x, x16, ROWS * DMODEL);
    transpose_cvt<<<dim3(3 * DMODEL / 32, DMODEL / 32), tb>>>(w_attn,  wattnT,  DMODEL, 3 * DMODEL);
    transpose_cvt<<<dim3(DMODEL / 32,     DMODEL / 32), tb>>>(w_aproj, waprojT, DMODEL, DMODEL);
    transpose_cvt<<<dim3(DFF / 32,        DMODEL / 32), tb>>>(w_fc,    wfcT,    DMODEL, DFF);
    transpose_cvt<<<dim3(DMODEL / 32,     DFF / 32),    tb>>>(w_mproj, wmprojT, DFF,    DMODEL);

    // qkv = x @ w_attn + b_attn  (scattered into per-head q/k/v)
    gemm_kernel<EPI_QKV><<<dim3(3 * DMODEL / GB_BN, ROWS / GB_BM), 256>>>(
        x16, wattnT, b_attn, nullptr, nullptr, q16, k16, v16, ROWS, 3 * DMODEL, DMODEL);

    // causal flash attention
    attn_kernel<<<dim3(SEQ / AT_BQ, BATCH * NHEAD), 256>>>(q16, k16, v16, a16);

    // aproj
    gemm_kernel<EPI_F32><<<dim3(DMODEL / GB_BN, ROWS / GB_BM), 256>>>(
        a16, waprojT, b_aproj, ap32, nullptr, nullptr, nullptr, nullptr,
        ROWS, DMODEL, DMODEL);

    // n = LN(x + aproj)
    ln_kernel<<<ROWS, 256>>>(x, ap32, g1, b1, n32, n16);

    // h = gelu(n @ w_fc + b_fc)
    gemm_kernel<EPI_GELU><<<dim3(DFF / GB_BN, ROWS / GB_BM), 256>>>(
        n16, wfcT, b_fc, nullptr, h16, nullptr, nullptr, nullptr,
        ROWS, DFF, DMODEL);

    // m = h @ w_mproj + b_mproj
    gemm_kernel<EPI_F32><<<dim3(DMODEL / GB_BN, ROWS / GB_BM), 256>>>(
        h16, wmprojT, b_mproj, m32, nullptr, nullptr, nullptr, nullptr,
        ROWS, DMODEL, DFF);

    // out = LN(n + m)
    ln_kernel<<<ROWS, 256>>>(n32, m32, g2, b2, out, nullptr);
}

// round 4
// speedup vs baseline: 1.0522x; 1.0522x over previous
#include <cuda_runtime.h>
#include <cuda_fp16.h>
#include <cstdint>
#include <cstddef>

// ---------------------------------------------------------------------------
// GPT-2 transformer block. mma.sync + ldmatrix + cp.async (tcgen05 is rejected
// by the harness's compute_103 PTX stage). fp32 I/O, fp16 compute, fp32 acc.
// ---------------------------------------------------------------------------

#define BATCH  4
#define SEQ    2048
#define DMODEL 1024
#define NHEAD  16
#define HDIM   64
#define DFF    4096
#define ROWS   (BATCH * SEQ)

// -------------------------- scratch (device globals) ----------------------
__device__ __half g_x16    [(size_t)ROWS * DMODEL];
__device__ __half g_wattnT [(size_t)3 * DMODEL * DMODEL];
__device__ __half g_waprojT[(size_t)DMODEL * DMODEL];
__device__ __half g_wfcT   [(size_t)DFF * DMODEL];
__device__ __half g_wmprojT[(size_t)DMODEL * DFF];
__device__ __half g_q16    [(size_t)ROWS * DMODEL];
__device__ __half g_k16    [(size_t)ROWS * DMODEL];
__device__ __half g_v16    [(size_t)ROWS * DMODEL];
__device__ __half g_a16    [(size_t)ROWS * DMODEL];
__device__ float  g_ap32   [(size_t)ROWS * DMODEL];
__device__ float  g_n32    [(size_t)ROWS * DMODEL];
__device__ __half g_n16    [(size_t)ROWS * DMODEL];
__device__ __half g_h16    [(size_t)ROWS * DFF];
__device__ float  g_m32    [(size_t)ROWS * DMODEL];

// ------------------------------ helpers -----------------------------------
__device__ __forceinline__ void mma16816(float c[4], const uint32_t a[4],
                                         const uint32_t b[2]) {
    asm volatile(
        "mma.sync.aligned.m16n8k16.row.col.f32.f16.f16.f32 "
        "{%0,%1,%2,%3}, {%4,%5,%6,%7}, {%8,%9}, {%0,%1,%2,%3};\n"
        : "+f"(c[0]), "+f"(c[1]), "+f"(c[2]), "+f"(c[3])
        : "r"(a[0]), "r"(a[1]), "r"(a[2]), "r"(a[3]), "r"(b[0]), "r"(b[1]));
}

__device__ __forceinline__ void ldsm_x4(uint32_t r[4], uint32_t addr) {
    asm volatile("ldmatrix.sync.aligned.m8n8.x4.shared.b16 {%0,%1,%2,%3}, [%4];"
                 : "=r"(r[0]), "=r"(r[1]), "=r"(r[2]), "=r"(r[3]) : "r"(addr));
}

__device__ __forceinline__ void cp_async16(uint32_t smem, const void* gptr) {
    asm volatile("cp.async.cg.shared.global [%0], [%1], 16;\n" ::"r"(smem), "l"(gptr));
}
#define CP_COMMIT() asm volatile("cp.async.commit_group;\n" ::)
#define CP_WAIT(n)  asm volatile("cp.async.wait_group %0;\n" ::"n"(n))

__device__ __forceinline__ uint32_t smem_u32(const void* p) {
    uint32_t a;
    asm("{ .reg .u64 t; cvta.to.shared.u64 t, %1; cvt.u32.u64 %0, t; }"
        : "=r"(a) : "l"(p));
    return a;
}

__device__ __forceinline__ uint32_t pack_half2f(float a, float b) {
    __half2 h = __floats2half2_rn(a, b);
    return *reinterpret_cast<uint32_t*>(&h);
}

__device__ __forceinline__ float fast_exp2(float x) {
    float r;
    asm("ex2.approx.f32 %0, %1;" : "=f"(r) : "f"(x));
    return r;
}

__device__ __forceinline__ float gelu_f(float x) {
    const float k0 = 0.7978845608028654f;
    float u = k0 * (x + 0.044715f * x * x * x);
    float t;
    asm("tanh.approx.f32 %0, %1;" : "=f"(t) : "f"(u));
    return 0.5f * x * (1.0f + t);
}

// ------------------------- conversion kernels -----------------------------
__global__ void cvt_f32_to_f16(const float* __restrict__ in,
                               __half* __restrict__ out, int n) {
    int i = blockIdx.x * blockDim.x + threadIdx.x;
    if (i < n) out[i] = __float2half(in[i]);
}

__global__ void transpose_cvt(const float* __restrict__ in,
                              __half* __restrict__ out, int R, int C) {
    __shared__ float t[32][33];
    int c = blockIdx.x * 32 + threadIdx.x;
    int r = blockIdx.y * 32 + threadIdx.y;
#pragma unroll
    for (int i = 0; i < 32; i += 8)
        t[threadIdx.y + i][threadIdx.x] = in[(size_t)(r + i) * C + c];
    __syncthreads();
    int oc   = blockIdx.y * 32 + threadIdx.x;
    int orow = blockIdx.x * 32 + threadIdx.y;
#pragma unroll
    for (int i = 0; i < 32; i += 8)
        out[(size_t)(orow + i) * R + oc] = __float2half(t[threadIdx.x][threadIdx.y + i]);
}

// ------------------------------- GEMM v2 -----------------------------------
// C[M,N] = A[M,K](f16 rm) * Bt[N,K](f16) + bias. CTA 128x256, 256 threads,
// warp grid 2(m) x 4(n), warp tile 64x64, BK=32, 4-stage cp.async pipeline,
// ldmatrix.x4 fragment loads. Rows padded to 40 halves (80B): conflict-free.
#define GB_BM 128
#define GB_BN 256
#define GB_BK 32
#define LKB   80                        // bytes per smem row
#define A_STG (GB_BM * LKB)             // 10240 B
#define B_STG (GB_BN * LKB)             // 20480 B
#define STG   (A_STG + B_STG)           // 30720 B
#define NSTG  4
#define GSMEM (NSTG * STG)              // 122880 B

enum { EPI_QKV = 0, EPI_F32 = 1, EPI_GELU = 2 };

template <int EPI>
__global__ __launch_bounds__(256, 1) void gemm_v2(
    const __half* __restrict__ A, const __half* __restrict__ Bt,
    const float* __restrict__ bias,
    float* __restrict__ outF, __half* __restrict__ outH,
    __half* __restrict__ oq, __half* __restrict__ ok, __half* __restrict__ ov,
    int N, int K) {
    extern __shared__ __align__(128) char smem[];
    const uint32_t sb = smem_u32(smem);

    const int tid  = threadIdx.x;
    const int warp = tid >> 5, lane = tid & 31;
    const int g = lane >> 2, tg = lane & 3;
    const int wm = warp >> 2, wn = warp & 3;
    const int bm = blockIdx.y * GB_BM, bn = blockIdx.x * GB_BN;
    const int KT = K / GB_BK;

    float acc[4][8][4];
#pragma unroll
    for (int i = 0; i < 4; i++)
#pragma unroll
        for (int j = 0; j < 8; j++)
#pragma unroll
            for (int q = 0; q < 4; q++) acc[i][j][q] = 0.f;

    // ldmatrix per-lane base addresses (within a stage)
    const uint32_t a_lm = (uint32_t)((lane & 15) * LKB + (lane >> 4) * 16) +
                          (uint32_t)(wm * 64 * LKB);
    const uint32_t b_lm = (uint32_t)(((lane & 7) + ((lane >> 4) << 3)) * LKB +
                                     ((lane >> 3) & 1) * 16) +
                          (uint32_t)(wn * 64 * LKB) + A_STG;

    auto load_tile = [&](int kt, int s) {
        const int k0 = kt * GB_BK;
        const uint32_t base = sb + s * STG;
        // A: 128 rows x 32 halves = 512 16B-chunks
#pragma unroll
        for (int i = 0; i < 2; i++) {
            int c = tid + i * 256;
            int row = c >> 2, kc = c & 3;
            cp_async16(base + row * LKB + kc * 16,
                       &A[(size_t)(bm + row) * K + k0 + kc * 8]);
        }
        // B: 256 rows x 32 halves = 1024 chunks
#pragma unroll
        for (int i = 0; i < 4; i++) {
            int c = tid + i * 256;
            int row = c >> 2, kc = c & 3;
            cp_async16(base + A_STG + row * LKB + kc * 16,
                       &Bt[(size_t)(bn + row) * K + k0 + kc * 8]);
        }
        CP_COMMIT();
    };

    load_tile(0, 0);
    load_tile(1, 1);
    load_tile(2, 2);

    for (int t = 0; t < KT; t++) {
        CP_WAIT(2);
        __syncthreads();
        if (t + 3 < KT) load_tile(t + 3, (t + 3) & 3);

        const uint32_t stg = sb + (t & 3) * STG;
#pragma unroll
        for (int kk = 0; kk < 2; kk++) {
            uint32_t a[4][4], b[8][2];
#pragma unroll
            for (int mi = 0; mi < 4; mi++)
                ldsm_x4(a[mi], stg + a_lm + mi * 16 * LKB + kk * 32);
#pragma unroll
            for (int nj = 0; nj < 4; nj++) {
                uint32_t r[4];
                ldsm_x4(r, stg + b_lm + nj * 16 * LKB + kk * 32);
                b[nj * 2][0] = r[0]; b[nj * 2][1] = r[1];
                b[nj * 2 + 1][0] = r[2]; b[nj * 2 + 1][1] = r[3];
            }
#pragma unroll
            for (int mi = 0; mi < 4; mi++)
#pragma unroll
                for (int ni = 0; ni < 8; ni++)
                    mma16816(acc[mi][ni], a[mi], b[ni]);
        }
        __syncthreads();
    }

    // ------------------------------ epilogue -------------------------------
#pragma unroll
    for (int mi = 0; mi < 4; mi++) {
        int r0 = bm + wm * 64 + mi * 16 + g;
        int r1 = r0 + 8;
#pragma unroll
        for (int ni = 0; ni < 8; ni++) {
            int c0 = bn + wn * 64 + ni * 8 + tg * 2;
            float bv0 = __ldg(&bias[c0]), bv1 = __ldg(&bias[c0 + 1]);
            float v00 = acc[mi][ni][0] + bv0, v01 = acc[mi][ni][1] + bv1;
            float v10 = acc[mi][ni][2] + bv0, v11 = acc[mi][ni][3] + bv1;
            if (EPI == EPI_F32) {
                *reinterpret_cast<float2*>(&outF[(size_t)r0 * N + c0]) =
                    make_float2(v00, v01);
                *reinterpret_cast<float2*>(&outF[(size_t)r1 * N + c0]) =
                    make_float2(v10, v11);
            } else if (EPI == EPI_GELU) {
                *reinterpret_cast<uint32_t*>(&outH[(size_t)r0 * N + c0]) =
                    pack_half2f(gelu_f(v00), gelu_f(v01));
                *reinterpret_cast<uint32_t*>(&outH[(size_t)r1 * N + c0]) =
                    pack_half2f(gelu_f(v10), gelu_f(v11));
            } else {  // EPI_QKV: scatter into per-head [B*H][S][hd]
                int which = c0 >> 10;
                int cc = c0 & 1023;
                int h = cc >> 6, d0 = cc & 63;
                __half* dst = which == 0 ? oq : which == 1 ? ok : ov;
                int b0i = r0 >> 11, s0i = r0 & 2047;
                int b1i = r1 >> 11, s1i = r1 & 2047;
                size_t i0 = ((size_t)(b0i * NHEAD + h) * SEQ + s0i) * HDIM + d0;
                size_t i1 = ((size_t)(b1i * NHEAD + h) * SEQ + s1i) * HDIM + d0;
                *reinterpret_cast<uint32_t*>(&dst[i0]) = pack_half2f(v00, v01);
                *reinterpret_cast<uint32_t*>(&dst[i1]) = pack_half2f(v10, v11);
            }
        }
    }
}

// --------------------------- flash attention -------------------------------
// grid (S/128, B*H), 256 threads (8 warps x 16 query rows). Causal.
// Softmax in log2-domain: P computed with ex2.approx.f16x2 (h2exp2).
#define AT_BQ 128
#define AT_BK 128
#define AT_LK 72
#define AT_LV 138

__global__ __launch_bounds__(256, 1) void attn_kernel(
    const __half* __restrict__ Q, const __half* __restrict__ K,
    const __half* __restrict__ V, __half* __restrict__ Aout) {
    __shared__ __half Ks[AT_BK][AT_LK];
    __shared__ __half Vt[HDIM][AT_LV];

    const int tid  = threadIdx.x;
    const int warp = tid >> 5, lane = tid & 31;
    const int g = lane >> 2, tg = lane & 3;
    const int bh = blockIdx.y;
    const int qb = blockIdx.x;
    const size_t base = (size_t)bh * SEQ * HDIM;

    for (int i = tid; i < AT_BQ * 8; i += 256) {
        int row = i >> 3, ch = (i & 7) * 8;
        *reinterpret_cast<uint4*>(&Ks[row][ch]) =
            *reinterpret_cast<const uint4*>(&Q[base + (size_t)(qb * AT_BQ + row) * HDIM + ch]);
    }
    __syncthreads();
    uint32_t qa[4][4];
    {
        int r = warp * 16 + g;
#pragma unroll
        for (int kt = 0; kt < 4; kt++) {
            int kb = kt * 16 + tg * 2;
            qa[kt][0] = *reinterpret_cast<const uint32_t*>(&Ks[r][kb]);
            qa[kt][1] = *reinterpret_cast<const uint32_t*>(&Ks[r + 8][kb]);
            qa[kt][2] = *reinterpret_cast<const uint32_t*>(&Ks[r][kb + 8]);
            qa[kt][3] = *reinterpret_cast<const uint32_t*>(&Ks[r + 8][kb + 8]);
        }
    }
    __syncthreads();

    float o[8][4];
#pragma unroll
    for (int i = 0; i < 8; i++)
#pragma unroll
        for (int j = 0; j < 4; j++) o[i][j] = 0.f;
    float m0 = -1e30f, m1 = -1e30f, l0 = 0.f, l1 = 0.f;
    const int q0 = qb * AT_BQ + warp * 16 + g;
    const int q1 = q0 + 8;

    for (int kblk = 0; kblk <= qb; kblk++) {
        for (int i = tid; i < AT_BK * 8; i += 256) {
            int row = i >> 3, ch = (i & 7) * 8;
            *reinterpret_cast<uint4*>(&Ks[row][ch]) =
                *reinterpret_cast<const uint4*>(&K[base + (size_t)(kblk * AT_BK + row) * HDIM + ch]);
        }
        for (int i = tid; i < AT_BK * HDIM; i += 256) {
            int s = i >> 6, d = i & 63;
            Vt[d][s] = V[base + (size_t)(kblk * AT_BK + s) * HDIM + d];
        }
        __syncthreads();

        float sacc[16][4];
#pragma unroll
        for (int nt = 0; nt < 16; nt++)
#pragma unroll
            for (int j = 0; j < 4; j++) sacc[nt][j] = 0.f;
#pragma unroll
        for (int kt = 0; kt < 4; kt++) {
#pragma unroll
            for (int nt = 0; nt < 16; nt++) {
                uint32_t b[2];
                int col = nt * 8 + g;
                int kb = kt * 16 + tg * 2;
                b[0] = *reinterpret_cast<const uint32_t*>(&Ks[col][kb]);
                b[1] = *reinterpret_cast<const uint32_t*>(&Ks[col][kb + 8]);
                mma16816(sacc[nt], qa[kt], b);
            }
        }

        // scale into log2 domain: 1/sqrt(64) * log2(e)
        const float scale = 0.18033688011112042f;
        const int kbase = kblk * AT_BK;
#pragma unroll
        for (int nt = 0; nt < 16; nt++) {
            int c0 = kbase + nt * 8 + tg * 2;
            sacc[nt][0] *= scale; sacc[nt][1] *= scale;
            sacc[nt][2] *= scale; sacc[nt][3] *= scale;
            if (kblk == qb) {
                if (c0 > q0)     sacc[nt][0] = -1e30f;
                if (c0 + 1 > q0) sacc[nt][1] = -1e30f;
                if (c0 > q1)     sacc[nt][2] = -1e30f;
                if (c0 + 1 > q1) sacc[nt][3] = -1e30f;
            }
        }

        float nm0 = m0, nm1 = m1;
#pragma unroll
        for (int nt = 0; nt < 16; nt++) {
            nm0 = fmaxf(nm0, fmaxf(sacc[nt][0], sacc[nt][1]));
            nm1 = fmaxf(nm1, fmaxf(sacc[nt][2], sacc[nt][3]));
        }
        nm0 = fmaxf(nm0, __shfl_xor_sync(0xffffffffu, nm0, 1));
        nm0 = fmaxf(nm0, __shfl_xor_sync(0xffffffffu, nm0, 2));
        nm1 = fmaxf(nm1, __shfl_xor_sync(0xffffffffu, nm1, 1));
        nm1 = fmaxf(nm1, __shfl_xor_sync(0xffffffffu, nm1, 2));
        float alpha0 = fast_exp2(m0 - nm0), alpha1 = fast_exp2(m1 - nm1);

        float ls0 = 0.f, ls1 = 0.f;
        uint32_t pa[8][4];
#pragma unroll
        for (int nt = 0; nt < 16; nt++) {
            __half2 e0 = h2exp2(__floats2half2_rn(sacc[nt][0] - nm0,
                                                  sacc[nt][1] - nm0));
            __half2 e1 = h2exp2(__floats2half2_rn(sacc[nt][2] - nm1,
                                                  sacc[nt][3] - nm1));
            float2 f0 = __half22float2(e0);
            float2 f1 = __half22float2(e1);
            ls0 += f0.x + f0.y;
            ls1 += f1.x + f1.y;
            int kt = nt >> 1, hi = nt & 1;
            pa[kt][hi * 2 + 0] = *reinterpret_cast<uint32_t*>(&e0);
            pa[kt][hi * 2 + 1] = *reinterpret_cast<uint32_t*>(&e1);
        }
        ls0 += __shfl_xor_sync(0xffffffffu, ls0, 1);
        ls0 += __shfl_xor_sync(0xffffffffu, ls0, 2);
        ls1 += __shfl_xor_sync(0xffffffffu, ls1, 1);
        ls1 += __shfl_xor_sync(0xffffffffu, ls1, 2);
        l0 = l0 * alpha0 + ls0;
        l1 = l1 * alpha1 + ls1;
        m0 = nm0;
        m1 = nm1;
#pragma unroll
        for (int dnt = 0; dnt < 8; dnt++) {
            o[dnt][0] *= alpha0; o[dnt][1] *= alpha0;
            o[dnt][2] *= alpha1; o[dnt][3] *= alpha1;
        }

#pragma unroll
        for (int kt = 0; kt < 8; kt++) {
#pragma unroll
            for (int dnt = 0; dnt < 8; dnt++) {
                uint32_t b[2];
                int d = dnt * 8 + g;
                b[0] = *reinterpret_cast<const uint32_t*>(&Vt[d][kt * 16 + tg * 2]);
                b[1] = *reinterpret_cast<const uint32_t*>(&Vt[d][kt * 16 + 8 + tg * 2]);
                mma16816(o[dnt], pa[kt], b);
            }
        }
        __syncthreads();
    }

    float inv0 = 1.f / l0, inv1 = 1.f / l1;
    int b = bh >> 4, h = bh & 15;
    int s0 = qb * AT_BQ + warp * 16 + g;
    size_t r0 = (size_t)(b * SEQ + s0) * DMODEL + h * HDIM;
    size_t r1 = r0 + (size_t)8 * DMODEL;
#pragma unroll
    for (int dnt = 0; dnt < 8; dnt++) {
        int d = dnt * 8 + tg * 2;
        *reinterpret_cast<uint32_t*>(&Aout[r0 + d]) =
            pack_half2f(o[dnt][0] * inv0, o[dnt][1] * inv0);
        *reinterpret_cast<uint32_t*>(&Aout[r1 + d]) =
            pack_half2f(o[dnt][2] * inv1, o[dnt][3] * inv1);
    }
}

// --------------------------- residual + layernorm --------------------------
__global__ __launch_bounds__(256) void ln_kernel(
    const float* __restrict__ X, const float* __restrict__ Y,
    const float* __restrict__ gg, const float* __restrict__ bb,
    float* __restrict__ out32, __half* __restrict__ out16) {
    const int row = blockIdx.x, tid = threadIdx.x;
    const float* x = X + (size_t)row * DMODEL;
    const float* y = Y + (size_t)row * DMODEL;
    float v[4];
    float s = 0.f;
#pragma unroll
    for (int i = 0; i < 4; i++) {
        int c = tid + i * 256;
        v[i] = x[c] + y[c];
        s += v[i];
    }
    __shared__ float red[8], red2[8];
#pragma unroll
    for (int o = 16; o; o >>= 1) s += __shfl_xor_sync(0xffffffffu, s, o);
    if ((tid & 31) == 0) red[tid >> 5] = s;
    __syncthreads();
    float tot = 0.f;
#pragma unroll
    for (int i = 0; i < 8; i++) tot += red[i];
    float mean = tot * (1.0f / DMODEL);

    float s2 = 0.f;
#pragma unroll
    for (int i = 0; i < 4; i++) {
        float d = v[i] - mean;
        s2 += d * d;
    }
#pragma unroll
    for (int o = 16; o; o >>= 1) s2 += __shfl_xor_sync(0xffffffffu, s2, o);
    if ((tid & 31) == 0) red2[tid >> 5] = s2;
    __syncthreads();
    float tot2 = 0.f;
#pragma unroll
    for (int i = 0; i < 8; i++) tot2 += red2[i];
    float rstd = rsqrtf(tot2 * (1.0f / DMODEL) + 1e-5f);

#pragma unroll
    for (int i = 0; i < 4; i++) {
        int c = tid + i * 256;
        float nv = (v[i] - mean) * rstd * gg[c] + bb[c];
        out32[(size_t)row * DMODEL + c] = nv;
        if (out16) out16[(size_t)row * DMODEL + c] = __float2half(nv);
    }
}

// ------------------------------- host --------------------------------------
extern "C" void kernel_launch(void* const* d_in, const int* in_sizes, int n_in,
                              void* d_out, int out_size) {
    const float* x       = (const float*)d_in[0];
    const float* w_attn  = (const float*)d_in[1];
    const float* b_attn  = (const float*)d_in[2];
    const float* w_aproj = (const float*)d_in[3];
    const float* b_aproj = (const float*)d_in[4];
    const float* g1      = (const float*)d_in[5];
    const float* b1      = (const float*)d_in[6];
    const float* w_fc    = (const float*)d_in[7];
    const float* b_fc    = (const float*)d_in[8];
    const float* w_mproj = (const float*)d_in[9];
    const float* b_mproj = (const float*)d_in[10];
    const float* g2      = (const float*)d_in[11];
    const float* b2      = (const float*)d_in[12];
    float* out = (float*)d_out;

    __half *x16, *wattnT, *waprojT, *wfcT, *wmprojT, *q16, *k16, *v16, *a16, *n16, *h16;
    float *ap32, *n32, *m32;
    cudaGetSymbolAddress((void**)&x16,     g_x16);
    cudaGetSymbolAddress((void**)&wattnT,  g_wattnT);
    cudaGetSymbolAddress((void**)&waprojT, g_waprojT);
    cudaGetSymbolAddress((void**)&wfcT,    g_wfcT);
    cudaGetSymbolAddress((void**)&wmprojT, g_wmprojT);
    cudaGetSymbolAddress((void**)&q16,     g_q16);
    cudaGetSymbolAddress((void**)&k16,     g_k16);
    cudaGetSymbolAddress((void**)&v16,     g_v16);
    cudaGetSymbolAddress((void**)&a16,     g_a16);
    cudaGetSymbolAddress((void**)&n16,     g_n16);
    cudaGetSymbolAddress((void**)&h16,     g_h16);
    cudaGetSymbolAddress((void**)&ap32,    g_ap32);
    cudaGetSymbolAddress((void**)&n32,     g_n32);
    cudaGetSymbolAddress((void**)&m32,     g_m32);

    cudaFuncSetAttribute(gemm_v2<EPI_QKV>,  cudaFuncAttributeMaxDynamicSharedMemorySize, GSMEM);
    cudaFuncSetAttribute(gemm_v2<EPI_F32>,  cudaFuncAttributeMaxDynamicSharedMemorySize, GSMEM);
    cudaFuncSetAttribute(gemm_v2<EPI_GELU>, cudaFuncAttributeMaxDynamicSharedMemorySize, GSMEM);

    dim3 tb(32, 8);
    cvt_f32_to_f16<<<(ROWS * DMODEL) / 256, 256>>>(x, x16, ROWS * DMODEL);
    transpose_cvt<<<dim3(3 * DMODEL / 32, DMODEL / 32), tb>>>(w_attn,  wattnT,  DMODEL, 3 * DMODEL);
    transpose_cvt<<<dim3(DMODEL / 32,     DMODEL / 32), tb>>>(w_aproj, waprojT, DMODEL, DMODEL);
    transpose_cvt<<<dim3(DFF / 32,        DMODEL / 32), tb>>>(w_fc,    wfcT,    DMODEL, DFF);
    transpose_cvt<<<dim3(DMODEL / 32,     DFF / 32),    tb>>>(w_mproj, wmprojT, DFF,    DMODEL);

    // qkv = x @ w_attn + b_attn (scatter into per-head q/k/v)
    gemm_v2<EPI_QKV><<<dim3(3 * DMODEL / GB_BN, ROWS / GB_BM), 256, GSMEM>>>(
        x16, wattnT, b_attn, nullptr, nullptr, q16, k16, v16, 3 * DMODEL, DMODEL);

    // causal flash attention
    attn_kernel<<<dim3(SEQ / AT_BQ, BATCH * NHEAD), 256>>>(q16, k16, v16, a16);

    // aproj
    gemm_v2<EPI_F32><<<dim3(DMODEL / GB_BN, ROWS / GB_BM), 256, GSMEM>>>(
        a16, waprojT, b_aproj, ap32, nullptr, nullptr, nullptr, nullptr,
        DMODEL, DMODEL);

    // n = LN(x + aproj)
    ln_kernel<<<ROWS, 256>>>(x, ap32, g1, b1, n32, n16);

    // h = gelu(n @ w_fc + b_fc)
    gemm_v2<EPI_GELU><<<dim3(DFF / GB_BN, ROWS / GB_BM), 256, GSMEM>>>(
        n16, wfcT, b_fc, nullptr, h16, nullptr, nullptr, nullptr,
        DFF, DMODEL);

    // m = h @ w_mproj + b_mproj
    gemm_v2<EPI_F32><<<dim3(DMODEL / GB_BN, ROWS / GB_BM), 256, GSMEM>>>(
        h16, wmprojT, b_mproj, m32, nullptr, nullptr, nullptr, nullptr,
        DMODEL, DFF);

    // out = LN(n + m)
    ln_kernel<<<ROWS, 256>>>(n32, m32, g2, b2, out, nullptr);
}

// round 5
// speedup vs baseline: 1.5452x; 1.4686x over previous
#include <cuda_runtime.h>
#include <cuda_fp16.h>
#include <cstdint>
#include <cstddef>

// ---------------------------------------------------------------------------
// GPT-2 transformer block. mma.sync + ldmatrix + cp.async (tcgen05 rejected by
// the harness's compute_103 PTX stage). fp32 I/O, fp16 compute, fp32 acc.
// ---------------------------------------------------------------------------

#define BATCH  4
#define SEQ    2048
#define DMODEL 1024
#define NHEAD  16
#define HDIM   64
#define DFF    4096
#define ROWS   (BATCH * SEQ)

// -------------------------- scratch (device globals) ----------------------
__device__ __half g_x16    [(size_t)ROWS * DMODEL];
__device__ __half g_wattnT [(size_t)3 * DMODEL * DMODEL];
__device__ __half g_waprojT[(size_t)DMODEL * DMODEL];
__device__ __half g_wfcT   [(size_t)DFF * DMODEL];
__device__ __half g_wmprojT[(size_t)DMODEL * DFF];
__device__ __half g_q16    [(size_t)ROWS * DMODEL];
__device__ __half g_k16    [(size_t)ROWS * DMODEL];
__device__ __half g_v16    [(size_t)ROWS * DMODEL];
__device__ __half g_a16    [(size_t)ROWS * DMODEL];
__device__ float  g_ap32   [(size_t)ROWS * DMODEL];
__device__ float  g_n32    [(size_t)ROWS * DMODEL];
__device__ __half g_n16    [(size_t)ROWS * DMODEL];
__device__ __half g_h16    [(size_t)ROWS * DFF];
__device__ float  g_m32    [(size_t)ROWS * DMODEL];

// ------------------------------ helpers -----------------------------------
__device__ __forceinline__ void mma16816(float c[4], const uint32_t a[4],
                                         const uint32_t b[2]) {
    asm volatile(
        "mma.sync.aligned.m16n8k16.row.col.f32.f16.f16.f32 "
        "{%0,%1,%2,%3}, {%4,%5,%6,%7}, {%8,%9}, {%0,%1,%2,%3};\n"
        : "+f"(c[0]), "+f"(c[1]), "+f"(c[2]), "+f"(c[3])
        : "r"(a[0]), "r"(a[1]), "r"(a[2]), "r"(a[3]), "r"(b[0]), "r"(b[1]));
}

__device__ __forceinline__ void ldsm_x4(uint32_t r[4], uint32_t addr) {
    asm volatile("ldmatrix.sync.aligned.m8n8.x4.shared.b16 {%0,%1,%2,%3}, [%4];"
                 : "=r"(r[0]), "=r"(r[1]), "=r"(r[2]), "=r"(r[3]) : "r"(addr));
}

__device__ __forceinline__ void ldsm_x4_trans(uint32_t r[4], uint32_t addr) {
    asm volatile("ldmatrix.sync.aligned.m8n8.x4.trans.shared.b16 {%0,%1,%2,%3}, [%4];"
                 : "=r"(r[0]), "=r"(r[1]), "=r"(r[2]), "=r"(r[3]) : "r"(addr));
}

__device__ __forceinline__ void cp_async16(uint32_t smem, const void* gptr) {
    asm volatile("cp.async.cg.shared.global [%0], [%1], 16;\n" ::"r"(smem), "l"(gptr));
}
#define CP_COMMIT() asm volatile("cp.async.commit_group;\n" ::)
#define CP_WAIT(n)  asm volatile("cp.async.wait_group %0;\n" ::"n"(n))

__device__ __forceinline__ uint32_t smem_u32(const void* p) {
    uint32_t a;
    asm("{ .reg .u64 t; cvta.to.shared.u64 t, %1; cvt.u32.u64 %0, t; }"
        : "=r"(a) : "l"(p));
    return a;
}

__device__ __forceinline__ uint32_t pack_half2f(float a, float b) {
    __half2 h = __floats2half2_rn(a, b);
    return *reinterpret_cast<uint32_t*>(&h);
}

__device__ __forceinline__ float fast_exp2(float x) {
    float r;
    asm("ex2.approx.f32 %0, %1;" : "=f"(r) : "f"(x));
    return r;
}

__device__ __forceinline__ float gelu_f(float x) {
    const float k0 = 0.7978845608028654f;
    float u = k0 * (x + 0.044715f * x * x * x);
    float t;
    asm("tanh.approx.f32 %0, %1;" : "=f"(t) : "f"(u));
    return 0.5f * x * (1.0f + t);
}

// -------------------- fused prep: cvt + 4 weight transposes ----------------
// blocks [0,8192): x row -> fp16. blocks [8192,20480): 32x32 transpose tiles.
__global__ __launch_bounds__(256) void prep_all(
    const float* __restrict__ x, const float* __restrict__ w_attn,
    const float* __restrict__ w_aproj, const float* __restrict__ w_fc,
    const float* __restrict__ w_mproj,
    __half* __restrict__ x16, __half* __restrict__ wattnT,
    __half* __restrict__ waprojT, __half* __restrict__ wfcT,
    __half* __restrict__ wmprojT) {
    int blk = blockIdx.x;
    const int tid = threadIdx.x;
    if (blk < 8192) {
        size_t off = (size_t)blk * DMODEL;
        float4 v = reinterpret_cast<const float4*>(x + off)[tid];
        __half2 h0 = __floats2half2_rn(v.x, v.y);
        __half2 h1 = __floats2half2_rn(v.z, v.w);
        *reinterpret_cast<uint2*>(x16 + off + tid * 4) =
            make_uint2(*reinterpret_cast<uint32_t*>(&h0),
                       *reinterpret_cast<uint32_t*>(&h1));
        return;
    }
    blk -= 8192;
    const float* src;
    __half* dst;
    int R, C;
    if (blk < 3072)      { src = w_attn;  dst = wattnT;  R = 1024; C = 3072; }
    else if (blk < 4096) { blk -= 3072; src = w_aproj; dst = waprojT; R = 1024; C = 1024; }
    else if (blk < 8192) { blk -= 4096; src = w_fc;    dst = wfcT;    R = 1024; C = 4096; }
    else                 { blk -= 8192; src = w_mproj; dst = wmprojT; R = 4096; C = 1024; }
    const int tilesX = C / 32;
    const int tx = blk % tilesX, ty = blk / tilesX;
    __shared__ float t[32][33];
    const int lx = tid & 31, ly = tid >> 5;
    const int c = tx * 32 + lx, r = ty * 32 + ly;
#pragma unroll
    for (int i = 0; i < 32; i += 8)
        t[ly + i][lx] = src[(size_t)(r + i) * C + c];
    __syncthreads();
    const int oc = ty * 32 + lx, orow = tx * 32 + ly;
#pragma unroll
    for (int i = 0; i < 32; i += 8)
        dst[(size_t)(orow + i) * R + oc] = __float2half(t[lx][ly + i]);
}

// ------------------------------- GEMM v3 -----------------------------------
// C[M,N] = A[M,K](f16 rm) * Bt[N,K](f16) + bias. CTA 128x128, 256 threads,
// warp grid 2(m) x 4(n), warp tile 64x32, BK=64, 3-stage cp.async pipeline,
// 144B rows (stride/16 = 9, odd -> ldmatrix conflict-free). 2 CTAs/SM.
#define GB_BM 128
#define GB_BN 128
#define GB_BK 64
#define LKB   144                      // bytes per smem row (64 halves + pad)
#define A_STG (GB_BM * LKB)            // 18432 B
#define STG   (2 * A_STG)              // 36864 B (A + B)
#define NSTG  3
#define GSMEM (NSTG * STG)             // 110592 B

enum { EPI_QKV = 0, EPI_F32 = 1, EPI_GELU = 2 };

template <int EPI>
__global__ __launch_bounds__(256, 2) void gemm_v3(
    const __half* __restrict__ A, const __half* __restrict__ Bt,
    const float* __restrict__ bias,
    float* __restrict__ outF, __half* __restrict__ outH,
    __half* __restrict__ oq, __half* __restrict__ ok, __half* __restrict__ ov,
    int N, int K) {
    extern __shared__ __align__(128) char smem[];
    const uint32_t sb = smem_u32(smem);

    const int tid  = threadIdx.x;
    const int warp = tid >> 5, lane = tid & 31;
    const int g = lane >> 2, tg = lane & 3;
    const int wm = warp >> 2, wn = warp & 3;
    const int bm = blockIdx.y * GB_BM, bn = blockIdx.x * GB_BN;
    const int KT = K / GB_BK;

    float acc[4][4][4];
#pragma unroll
    for (int i = 0; i < 4; i++)
#pragma unroll
        for (int j = 0; j < 4; j++)
#pragma unroll
            for (int q = 0; q < 4; q++) acc[i][j][q] = 0.f;

    // ldmatrix lane addressing (within stage)
    const uint32_t a_lm = (uint32_t)((wm * 64 + (lane & 15)) * LKB + (lane >> 4) * 16);
    const uint32_t b_lm = (uint32_t)(A_STG +
        (wn * 32 + (lane & 7) + ((lane >> 4) << 3)) * LKB + ((lane >> 3) & 1) * 16);

    auto load_tile = [&](int kt, int s) {
        const int k0 = kt * GB_BK;
        const uint32_t base = sb + s * STG;
#pragma unroll
        for (int i = 0; i < 4; i++) {
            int idx = tid + i * 256;
            int row = idx >> 3, c = idx & 7;
            cp_async16(base + row * LKB + c * 16,
                       &A[(size_t)(bm + row) * K + k0 + c * 8]);
        }
#pragma unroll
        for (int i = 0; i < 4; i++) {
            int idx = tid + i * 256;
            int row = idx >> 3, c = idx & 7;
            cp_async16(base + A_STG + row * LKB + c * 16,
                       &Bt[(size_t)(bn + row) * K + k0 + c * 8]);
        }
        CP_COMMIT();
    };

    load_tile(0, 0);
    load_tile(1, 1);
    load_tile(2, 2);

    int stage = 0;
    for (int t = 0; t < KT; t++) {
        CP_WAIT(2);
        __syncthreads();
        const uint32_t stg = sb + stage * STG;
#pragma unroll
        for (int kk = 0; kk < 4; kk++) {
            uint32_t a[4][4], b[4][2];
#pragma unroll
            for (int mi = 0; mi < 4; mi++)
                ldsm_x4(a[mi], stg + a_lm + mi * 16 * LKB + kk * 32);
#pragma unroll
            for (int p = 0; p < 2; p++) {
                uint32_t r[4];
                ldsm_x4(r, stg + b_lm + p * 16 * LKB + kk * 32);
                b[p * 2][0] = r[0]; b[p * 2][1] = r[1];
                b[p * 2 + 1][0] = r[2]; b[p * 2 + 1][1] = r[3];
            }
#pragma unroll
            for (int mi = 0; mi < 4; mi++)
#pragma unroll
                for (int ni = 0; ni < 4; ni++)
                    mma16816(acc[mi][ni], a[mi], b[ni]);
        }
        __syncthreads();
        if (t + 3 < KT) load_tile(t + 3, stage);
        stage = (stage == 2) ? 0 : stage + 1;
    }

    // ------------------------------ epilogue -------------------------------
#pragma unroll
    for (int mi = 0; mi < 4; mi++) {
        int r0 = bm + wm * 64 + mi * 16 + g;
        int r1 = r0 + 8;
#pragma unroll
        for (int ni = 0; ni < 4; ni++) {
            int c0 = bn + wn * 32 + ni * 8 + tg * 2;
            float bv0 = __ldg(&bias[c0]), bv1 = __ldg(&bias[c0 + 1]);
            float v00 = acc[mi][ni][0] + bv0, v01 = acc[mi][ni][1] + bv1;
            float v10 = acc[mi][ni][2] + bv0, v11 = acc[mi][ni][3] + bv1;
            if (EPI == EPI_F32) {
                *reinterpret_cast<float2*>(&outF[(size_t)r0 * N + c0]) =
                    make_float2(v00, v01);
                *reinterpret_cast<float2*>(&outF[(size_t)r1 * N + c0]) =
                    make_float2(v10, v11);
            } else if (EPI == EPI_GELU) {
                *reinterpret_cast<uint32_t*>(&outH[(size_t)r0 * N + c0]) =
                    pack_half2f(gelu_f(v00), gelu_f(v01));
                *reinterpret_cast<uint32_t*>(&outH[(size_t)r1 * N + c0]) =
                    pack_half2f(gelu_f(v10), gelu_f(v11));
            } else {  // EPI_QKV: scatter into per-head [B*H][S][hd]
                int which = c0 >> 10;
                int cc = c0 & 1023;
                int h = cc >> 6, d0 = cc & 63;
                __half* dst = which == 0 ? oq : which == 1 ? ok : ov;
                int b0i = r0 >> 11, s0i = r0 & 2047;
                int b1i = r1 >> 11, s1i = r1 & 2047;
                size_t i0 = ((size_t)(b0i * NHEAD + h) * SEQ + s0i) * HDIM + d0;
                size_t i1 = ((size_t)(b1i * NHEAD + h) * SEQ + s1i) * HDIM + d0;
                *reinterpret_cast<uint32_t*>(&dst[i0]) = pack_half2f(v00, v01);
                *reinterpret_cast<uint32_t*>(&dst[i1]) = pack_half2f(v10, v11);
            }
        }
    }
}

// --------------------------- flash attention v2 ----------------------------
// grid (S/128, B*H), 256 threads (8 warps x 16 q rows). Causal. K,V row-major
// in smem, fragments via ldmatrix (V via .trans), cp.async double buffering.
#define AT_LKB 144                    // 64 halves + pad (stride/16 odd)
#define AT_KS  (128 * AT_LKB)         // 18432 B
#define AT_STG (2 * AT_KS)            // 36864 B (K + V)
#define ASMEM  (2 * AT_STG)           // 73728 B

__global__ __launch_bounds__(256, 1) void attn_kernel(
    const __half* __restrict__ Q, const __half* __restrict__ K,
    const __half* __restrict__ V, __half* __restrict__ Aout) {
    extern __shared__ __align__(128) char smem[];
    const uint32_t sb = smem_u32(smem);

    const int tid  = threadIdx.x;
    const int warp = tid >> 5, lane = tid & 31;
    const int g = lane >> 2, tg = lane & 3;
    const int bh = blockIdx.y;
    const int qb = blockIdx.x;
    const size_t base = (size_t)bh * SEQ * HDIM;

    // stage Q tile into stage-0 K area, extract A-fragments via ldmatrix
#pragma unroll
    for (int i = 0; i < 4; i++) {
        int idx = tid + i * 256;
        int row = idx >> 3, c = idx & 7;
        *reinterpret_cast<uint4*>(smem + row * AT_LKB + c * 16) =
            *reinterpret_cast<const uint4*>(
                &Q[base + (size_t)(qb * 128 + row) * HDIM + c * 8]);
    }
    __syncthreads();
    uint32_t qa[4][4];
    {
        const uint32_t q_lm = sb + (warp * 16 + (lane & 15)) * AT_LKB + (lane >> 4) * 16;
#pragma unroll
        for (int kt = 0; kt < 4; kt++) ldsm_x4(qa[kt], q_lm + kt * 32);
    }
    __syncthreads();

    // ldmatrix lane addressing for K (B-frag) and V (trans B-frag)
    const uint32_t k_lm = (uint32_t)(((lane & 7) + ((lane >> 4) << 3)) * AT_LKB +
                                     ((lane >> 3) & 1) * 16);
    const uint32_t v_lm = (uint32_t)(((lane & 7) + (((lane >> 3) & 1) << 3)) * AT_LKB +
                                     (lane >> 4) * 16);

    auto load_kv = [&](int kb, int s) {
        const uint32_t bs = sb + s * AT_STG;
#pragma unroll
        for (int i = 0; i < 4; i++) {
            int idx = tid + i * 256;
            int row = idx >> 3, c = idx & 7;
            cp_async16(bs + row * AT_LKB + c * 16,
                       &K[base + (size_t)(kb * 128 + row) * HDIM + c * 8]);
        }
#pragma unroll
        for (int i = 0; i < 4; i++) {
            int idx = tid + i * 256;
            int row = idx >> 3, c = idx & 7;
            cp_async16(bs + AT_KS + row * AT_LKB + c * 16,
                       &V[base + (size_t)(kb * 128 + row) * HDIM + c * 8]);
        }
        CP_COMMIT();
    };

    float o[8][4];
#pragma unroll
    for (int i = 0; i < 8; i++)
#pragma unroll
        for (int j = 0; j < 4; j++) o[i][j] = 0.f;
    float m0 = -1e30f, m1 = -1e30f, l0 = 0.f, l1 = 0.f;
    const int q0 = qb * 128 + warp * 16 + g;
    const int q1 = q0 + 8;

    load_kv(0, 0);

    for (int kblk = 0; kblk <= qb; kblk++) {
        if (kblk < qb) {
            load_kv(kblk + 1, (kblk + 1) & 1);
            CP_WAIT(1);
        } else {
            CP_WAIT(0);
        }
        __syncthreads();
        const uint32_t ks = sb + (kblk & 1) * AT_STG;
        const uint32_t vs = ks + AT_KS;

        // S = Q K^T  (K fragments via ldmatrix)
        float sacc[16][4];
#pragma unroll
        for (int nt = 0; nt < 16; nt++)
#pragma unroll
            for (int j = 0; j < 4; j++) sacc[nt][j] = 0.f;
#pragma unroll
        for (int kt = 0; kt < 4; kt++) {
#pragma unroll
            for (int pair = 0; pair < 8; pair++) {
                uint32_t r[4];
                ldsm_x4(r, ks + k_lm + pair * 16 * AT_LKB + kt * 32);
                mma16816(sacc[pair * 2],     qa[kt], r);
                mma16816(sacc[pair * 2 + 1], qa[kt], r + 2);
            }
        }

        // scale into log2 domain: 1/sqrt(64) * log2(e)
        const float scale = 0.18033688011112042f;
        const int kbase = kblk * 128;
#pragma unroll
        for (int nt = 0; nt < 16; nt++) {
            int c0 = kbase + nt * 8 + tg * 2;
            sacc[nt][0] *= scale; sacc[nt][1] *= scale;
            sacc[nt][2] *= scale; sacc[nt][3] *= scale;
            if (kblk == qb) {
                if (c0 > q0)     sacc[nt][0] = -1e30f;
                if (c0 + 1 > q0) sacc[nt][1] = -1e30f;
                if (c0 > q1)     sacc[nt][2] = -1e30f;
                if (c0 + 1 > q1) sacc[nt][3] = -1e30f;
            }
        }

        float nm0 = m0, nm1 = m1;
#pragma unroll
        for (int nt = 0; nt < 16; nt++) {
            nm0 = fmaxf(nm0, fmaxf(sacc[nt][0], sacc[nt][1]));
            nm1 = fmaxf(nm1, fmaxf(sacc[nt][2], sacc[nt][3]));
        }
        nm0 = fmaxf(nm0, __shfl_xor_sync(0xffffffffu, nm0, 1));
        nm0 = fmaxf(nm0, __shfl_xor_sync(0xffffffffu, nm0, 2));
        nm1 = fmaxf(nm1, __shfl_xor_sync(0xffffffffu, nm1, 1));
        nm1 = fmaxf(nm1, __shfl_xor_sync(0xffffffffu, nm1, 2));
        float alpha0 = fast_exp2(m0 - nm0), alpha1 = fast_exp2(m1 - nm1);

        float ls0 = 0.f, ls1 = 0.f;
        uint32_t pa[8][4];
#pragma unroll
        for (int nt = 0; nt < 16; nt++) {
            __half2 e0 = h2exp2(__floats2half2_rn(sacc[nt][0] - nm0,
                                                  sacc[nt][1] - nm0));
            __half2 e1 = h2exp2(__floats2half2_rn(sacc[nt][2] - nm1,
                                                  sacc[nt][3] - nm1));
            float2 f0 = __half22float2(e0);
            float2 f1 = __half22float2(e1);
            ls0 += f0.x + f0.y;
            ls1 += f1.x + f1.y;
            int kt = nt >> 1, hi = nt & 1;
            pa[kt][hi * 2 + 0] = *reinterpret_cast<uint32_t*>(&e0);
            pa[kt][hi * 2 + 1] = *reinterpret_cast<uint32_t*>(&e1);
        }
        ls0 += __shfl_xor_sync(0xffffffffu, ls0, 1);
        ls0 += __shfl_xor_sync(0xffffffffu, ls0, 2);
        ls1 += __shfl_xor_sync(0xffffffffu, ls1, 1);
        ls1 += __shfl_xor_sync(0xffffffffu, ls1, 2);
        l0 = l0 * alpha0 + ls0;
        l1 = l1 * alpha1 + ls1;
        m0 = nm0;
        m1 = nm1;
#pragma unroll
        for (int dnt = 0; dnt < 8; dnt++) {
            o[dnt][0] *= alpha0; o[dnt][1] *= alpha0;
            o[dnt][2] *= alpha1; o[dnt][3] *= alpha1;
        }

        // O += P V  (V fragments via ldmatrix.trans on row-major V)
#pragma unroll
        for (int kt = 0; kt < 8; kt++) {
#pragma unroll
            for (int dp = 0; dp < 4; dp++) {
                uint32_t r[4];
                ldsm_x4_trans(r, vs + v_lm + kt * 16 * AT_LKB + dp * 32);
                mma16816(o[dp * 2],     pa[kt], r);
                mma16816(o[dp * 2 + 1], pa[kt], r + 2);
            }
        }
        __syncthreads();
    }

    float inv0 = 1.f / l0, inv1 = 1.f / l1;
    int b = bh >> 4, h = bh & 15;
    int s0 = qb * 128 + warp * 16 + g;
    size_t r0 = (size_t)(b * SEQ + s0) * DMODEL + h * HDIM;
    size_t r1 = r0 + (size_t)8 * DMODEL;
#pragma unroll
    for (int dnt = 0; dnt < 8; dnt++) {
        int d = dnt * 8 + tg * 2;
        *reinterpret_cast<uint32_t*>(&Aout[r0 + d]) =
            pack_half2f(o[dnt][0] * inv0, o[dnt][1] * inv0);
        *reinterpret_cast<uint32_t*>(&Aout[r1 + d]) =
            pack_half2f(o[dnt][2] * inv1, o[dnt][3] * inv1);
    }
}

// --------------------------- residual + layernorm --------------------------
__global__ __launch_bounds__(256) void ln_kernel(
    const float* __restrict__ X, const float* __restrict__ Y,
    const float* __restrict__ gg, const float* __restrict__ bb,
    float* __restrict__ out32, __half* __restrict__ out16) {
    const int row = blockIdx.x, tid = threadIdx.x;
    const float* x = X + (size_t)row * DMODEL;
    const float* y = Y + (size_t)row * DMODEL;
    float v[4];
    float s = 0.f;
#pragma unroll
    for (int i = 0; i < 4; i++) {
        int c = tid + i * 256;
        v[i] = x[c] + y[c];
        s += v[i];
    }
    __shared__ float red[8], red2[8];
#pragma unroll
    for (int o = 16; o; o >>= 1) s += __shfl_xor_sync(0xffffffffu, s, o);
    if ((tid & 31) == 0) red[tid >> 5] = s;
    __syncthreads();
    float tot = 0.f;
#pragma unroll
    for (int i = 0; i < 8; i++) tot += red[i];
    float mean = tot * (1.0f / DMODEL);

    float s2 = 0.f;
#pragma unroll
    for (int i = 0; i < 4; i++) {
        float d = v[i] - mean;
        s2 += d * d;
    }
#pragma unroll
    for (int o = 16; o; o >>= 1) s2 += __shfl_xor_sync(0xffffffffu, s2, o);
    if ((tid & 31) == 0) red2[tid >> 5] = s2;
    __syncthreads();
    float tot2 = 0.f;
#pragma unroll
    for (int i = 0; i < 8; i++) tot2 += red2[i];
    float rstd = rsqrtf(tot2 * (1.0f / DMODEL) + 1e-5f);

#pragma unroll
    for (int i = 0; i < 4; i++) {
        int c = tid + i * 256;
        float nv = (v[i] - mean) * rstd * gg[c] + bb[c];
        out32[(size_t)row * DMODEL + c] = nv;
        if (out16) out16[(size_t)row * DMODEL + c] = __float2half(nv);
    }
}

// ------------------------------- host --------------------------------------
extern "C" void kernel_launch(void* const* d_in, const int* in_sizes, int n_in,
                              void* d_out, int out_size) {
    const float* x       = (const float*)d_in[0];
    const float* w_attn  = (const float*)d_in[1];
    const float* b_attn  = (const float*)d_in[2];
    const float* w_aproj = (const float*)d_in[3];
    const float* b_aproj = (const float*)d_in[4];
    const float* g1      = (const float*)d_in[5];
    const float* b1      = (const float*)d_in[6];
    const float* w_fc    = (const float*)d_in[7];
    const float* b_fc    = (const float*)d_in[8];
    const float* w_mproj = (const float*)d_in[9];
    const float* b_mproj = (const float*)d_in[10];
    const float* g2      = (const float*)d_in[11];
    const float* b2      = (const float*)d_in[12];
    float* out = (float*)d_out;

    __half *x16, *wattnT, *waprojT, *wfcT, *wmprojT, *q16, *k16, *v16, *a16, *n16, *h16;
    float *ap32, *n32, *m32;
    cudaGetSymbolAddress((void**)&x16,     g_x16);
    cudaGetSymbolAddress((void**)&wattnT,  g_wattnT);
    cudaGetSymbolAddress((void**)&waprojT, g_waprojT);
    cudaGetSymbolAddress((void**)&wfcT,    g_wfcT);
    cudaGetSymbolAddress((void**)&wmprojT, g_wmprojT);
    cudaGetSymbolAddress((void**)&q16,     g_q16);
    cudaGetSymbolAddress((void**)&k16,     g_k16);
    cudaGetSymbolAddress((void**)&v16,     g_v16);
    cudaGetSymbolAddress((void**)&a16,     g_a16);
    cudaGetSymbolAddress((void**)&n16,     g_n16);
    cudaGetSymbolAddress((void**)&h16,     g_h16);
    cudaGetSymbolAddress((void**)&ap32,    g_ap32);
    cudaGetSymbolAddress((void**)&n32,     g_n32);
    cudaGetSymbolAddress((void**)&m32,     g_m32);

    cudaFuncSetAttribute(gemm_v3<EPI_QKV>,  cudaFuncAttributeMaxDynamicSharedMemorySize, GSMEM);
    cudaFuncSetAttribute(gemm_v3<EPI_F32>,  cudaFuncAttributeMaxDynamicSharedMemorySize, GSMEM);
    cudaFuncSetAttribute(gemm_v3<EPI_GELU>, cudaFuncAttributeMaxDynamicSharedMemorySize, GSMEM);
    cudaFuncSetAttribute(attn_kernel,       cudaFuncAttributeMaxDynamicSharedMemorySize, ASMEM);

    // launch 0: fused prep (cvt + all weight transposes)
    prep_all<<<20480, 256>>>(x, w_attn, w_aproj, w_fc, w_mproj,
                             x16, wattnT, waprojT, wfcT, wmprojT);

    // launch 1: qkv = x @ w_attn + b_attn (scatter into per-head q/k/v)
    gemm_v3<EPI_QKV><<<dim3(3 * DMODEL / GB_BN, ROWS / GB_BM), 256, GSMEM>>>(
        x16, wattnT, b_attn, nullptr, nullptr, q16, k16, v16, 3 * DMODEL, DMODEL);

    // launch 2: causal flash attention
    attn_kernel<<<dim3(SEQ / 128, BATCH * NHEAD), 256, ASMEM>>>(q16, k16, v16, a16);

    // launch 3: aproj
    gemm_v3<EPI_F32><<<dim3(DMODEL / GB_BN, ROWS / GB_BM), 256, GSMEM>>>(
        a16, waprojT, b_aproj, ap32, nullptr, nullptr, nullptr, nullptr,
        DMODEL, DMODEL);

    // launch 4: n = LN(x + aproj)
    ln_kernel<<<ROWS, 256>>>(x, ap32, g1, b1, n32, n16);

    // launch 5: h = gelu(n @ w_fc + b_fc)   <- ncu -s 5 -c 1 captures this
    gemm_v3<EPI_GELU><<<dim3(DFF / GB_BN, ROWS / GB_BM), 256, GSMEM>>>(
        n16, wfcT, b_fc, nullptr, h16, nullptr, nullptr, nullptr,
        DFF, DMODEL);

    // launch 6: m = h @ w_mproj + b_mproj
    gemm_v3<EPI_F32><<<dim3(DMODEL / GB_BN, ROWS / GB_BM), 256, GSMEM>>>(
        h16, wmprojT, b_mproj, m32, nullptr, nullptr, nullptr, nullptr,
        DMODEL, DFF);

    // launch 7: out = LN(n + m)
    ln_kernel<<<ROWS, 256>>>(n32, m32, g2, b2, out, nullptr);
}